// round 3
// baseline (speedup 1.0000x reference)
#include <cuda_runtime.h>
#include <cstdint>

#define CC 96
#define HH 256
#define WW 256
#define KK 7

__device__ __forceinline__ void fma2(unsigned long long &d,
                                     unsigned long long a,
                                     unsigned long long b) {
    asm("fma.rn.f32x2 %0, %1, %2, %0;" : "+l"(d) : "l"(a), "l"(b));
}
__device__ __forceinline__ unsigned long long pk2(float lo, float hi) {
    return (unsigned long long)__float_as_uint(lo) |
           ((unsigned long long)__float_as_uint(hi) << 32);
}
__device__ __forceinline__ void upk2(unsigned long long v, float &lo, float &hi) {
    lo = __uint_as_float((unsigned int)(v & 0xffffffffull));
    hi = __uint_as_float((unsigned int)(v >> 32));
}

// blockDim=(32,2), grid=(2,1,nimg). Warp = 128 cols (lane*4), 128-row strip.
// Fast path (r < 5/3): folded 12-tap integer-offset conv.
//   H conv: 16-slot register ring, prefetch 6 rows ahead.
//   W conv: window from neighbor lanes via warp shuffle (no global side loads);
//           warp-edge lanes use predicated global loads (L1-resident).
__global__ __launch_bounds__(64) void caxial_kernel(const float* __restrict__ x,
                                                    const float* __restrict__ wh,
                                                    const float* __restrict__ ww,
                                                    const float* __restrict__ rp,
                                                    float* __restrict__ out) {
    const int c    = blockIdx.z % CC;
    const int lane = threadIdx.x;                       // 0..31
    const int x4   = blockIdx.x * 128 + lane * 4;       // global col base
    const int y0   = threadIdx.y * 128;                 // strip start
    const float* xc = x   + (size_t)blockIdx.z * (HH * WW);
    float*       oc = out + (size_t)blockIdx.z * (HH * WW);

    float rv = rp[0];
    if (rv < 1.0f) rv = 1.0f;

    float whv[KK], wwv[KK], fri[KK];
    int   k0i[KK];
    #pragma unroll
    for (int i = 0; i < KK; i++) {
        float ofr = (float)(i - 3) * rv;
        float fl  = floorf(ofr);
        k0i[i] = (int)fl + 6;
        fri[i] = ofr - fl;
        whv[i] = wh[c * KK + i];
        wwv[i] = ww[c * KK + i];
    }
    const bool fast = (k0i[0] >= 0) && (k0i[KK - 1] + 1 <= 11);

    if (fast) {
        // Fold 7 bilinear taps into 12 integer-offset weights (dc/dr = k - 6)
        unsigned long long cwh2[12];
        float cww[12];
        #pragma unroll
        for (int k = 0; k < 12; k++) {
            float sh = 0.f, sw = 0.f;
            #pragma unroll
            for (int i = 0; i < KK; i++) {
                if (k0i[i] == k)     { sh += whv[i] * (1.f - fri[i]); sw += wwv[i] * (1.f - fri[i]); }
                if (k0i[i] + 1 == k) { sh += whv[i] * fri[i];         sw += wwv[i] * fri[i]; }
            }
            cwh2[k] = pk2(sh, sh);
            cww[k]  = sw;
        }

        // Register ring: 16 rows, one float4 each. slot(row) = row & 15.
        ulonglong2 ring[16];
        #pragma unroll
        for (int t = -6; t <= 5; t++) {
            int row = y0 + t;
            ulonglong2 v = make_ulonglong2(0ull, 0ull);
            if (row >= 0)   // row < HH always true in prologue (y0 <= 128)
                v = *reinterpret_cast<const ulonglong2*>(xc + (size_t)row * WW + x4);
            ring[(t + 16) & 15] = v;
        }

        const bool eL0 = (lane < 2)  && (x4 >= 8);        // L2 pair via global
        const bool eL1 = (lane == 0) && (x4 >= 4);        // L1 quad via global
        const bool eR0 = (lane > 29) && (x4 + 11 < WW);   // R2 via global
        const bool eR1 = (lane == 31) && (x4 + 7 < WW);   // R1 quad via global
        const float4 z4 = make_float4(0.f, 0.f, 0.f, 0.f);
        const unsigned FULL = 0xffffffffu;

        #pragma unroll 1
        for (int half = 0; half < 8; half++) {
            int ybase = y0 + half * 16;
            #pragma unroll
            for (int u = 0; u < 16; u++) {
                int y = ybase + u;
                // Prefetch row y+6 into slot (u+6)&15
                {
                    int row = y + 6;
                    ulonglong2 v = make_ulonglong2(0ull, 0ull);
                    if (row < HH)
                        v = *reinterpret_cast<const ulonglong2*>(xc + (size_t)row * WW + x4);
                    ring[(u + 6) & 15] = v;
                }
                const float* rowp = xc + (size_t)y * WW;
                // Warp-edge fallback loads (predicated; inactive on 28/32 lanes)
                float4 gl0 = eL0 ? *reinterpret_cast<const float4*>(rowp + x4 - 8) : z4;
                float4 gl1 = eL1 ? *reinterpret_cast<const float4*>(rowp + x4 - 4) : z4;
                float4 gr0 = eR0 ? *reinterpret_cast<const float4*>(rowp + x4 + 8) : z4;
                float4 gr1 = eR1 ? *reinterpret_cast<const float4*>(rowp + x4 + 4) : z4;

                ulonglong2 ctr = ring[u & 15];       // row y, cols x4..x4+3
                float c0, c1, c2, c3;
                upk2(ctr.x, c0, c1);
                upk2(ctr.y, c2, c3);

                // identity + H conv (packed f32x2 FMAs)
                unsigned long long acc01 = ctr.x;
                unsigned long long acc23 = ctr.y;
                #pragma unroll
                for (int k = 0; k < 12; k++) {       // row y + (k-6)
                    ulonglong2 rv2 = ring[(u + k + 10) & 15];
                    fma2(acc01, cwh2[k], rv2.x);
                    fma2(acc23, cwh2[k], rv2.y);
                }
                float a0, a1, a2, a3;
                upk2(acc01, a0, a1);
                upk2(acc23, a2, a3);

                // W window cols x4-6..x4+8 from neighbor lanes (shuffle)
                float sL2a = __shfl_up_sync(FULL, c2, 2);
                float sL2b = __shfl_up_sync(FULL, c3, 2);
                float sL10 = __shfl_up_sync(FULL, c0, 1);
                float sL11 = __shfl_up_sync(FULL, c1, 1);
                float sL12 = __shfl_up_sync(FULL, c2, 1);
                float sL13 = __shfl_up_sync(FULL, c3, 1);
                float sR10 = __shfl_down_sync(FULL, c0, 1);
                float sR11 = __shfl_down_sync(FULL, c1, 1);
                float sR12 = __shfl_down_sync(FULL, c2, 1);
                float sR13 = __shfl_down_sync(FULL, c3, 1);
                float sR2a = __shfl_down_sync(FULL, c0, 2);

                float win[15];
                win[0]  = (lane >= 2)  ? sL2a : gl0.z;   // x4-6
                win[1]  = (lane >= 2)  ? sL2b : gl0.w;   // x4-5
                win[2]  = (lane >= 1)  ? sL10 : gl1.x;   // x4-4
                win[3]  = (lane >= 1)  ? sL11 : gl1.y;
                win[4]  = (lane >= 1)  ? sL12 : gl1.z;
                win[5]  = (lane >= 1)  ? sL13 : gl1.w;   // x4-1
                win[6]  = c0; win[7] = c1; win[8] = c2; win[9] = c3;
                win[10] = (lane <= 30) ? sR10 : gr1.x;   // x4+4
                win[11] = (lane <= 30) ? sR11 : gr1.y;
                win[12] = (lane <= 30) ? sR12 : gr1.z;
                win[13] = (lane <= 30) ? sR13 : gr1.w;   // x4+7
                win[14] = (lane <= 29) ? sR2a : gr0.x;   // x4+8

                #pragma unroll
                for (int k = 0; k < 12; k++) {       // col (x4+j) + (k-6) = win[k+j]
                    float w = cww[k];
                    a0 += w * win[k];
                    a1 += w * win[k + 1];
                    a2 += w * win[k + 2];
                    a3 += w * win[k + 3];
                }

                __stcs(reinterpret_cast<float4*>(oc + (size_t)y * WW + x4),
                       make_float4(a0, a1, a2, a3));
            }
        }
    } else {
        // Generic path: direct 7-tap bilinear gather along both axes.
        #pragma unroll 1
        for (int yy = 0; yy < 128; yy++) {
            int y = y0 + yy;
            float acc[4];
            #pragma unroll
            for (int j = 0; j < 4; j++) acc[j] = xc[(size_t)y * WW + x4 + j];
            #pragma unroll
            for (int i = 0; i < KK; i++) {
                int   d  = k0i[i] - 6;
                float fr = fri[i];
                int r0 = y + d, r1 = r0 + 1;
                #pragma unroll
                for (int j = 0; j < 4; j++) {
                    int col = x4 + j;
                    float s0 = (r0 >= 0 && r0 < HH) ? xc[(size_t)r0 * WW + col] : 0.f;
                    float s1 = (r1 >= 0 && r1 < HH) ? xc[(size_t)r1 * WW + col] : 0.f;
                    acc[j] += whv[i] * (s0 * (1.f - fr) + s1 * fr);
                    int c0i = col + d, c1i = c0i + 1;
                    float t0 = (c0i >= 0 && c0i < WW) ? xc[(size_t)y * WW + c0i] : 0.f;
                    float t1 = (c1i >= 0 && c1i < WW) ? xc[(size_t)y * WW + c1i] : 0.f;
                    acc[j] += wwv[i] * (t0 * (1.f - fr) + t1 * fr);
                }
            }
            #pragma unroll
            for (int j = 0; j < 4; j++) oc[(size_t)y * WW + x4 + j] = acc[j];
        }
    }
}

extern "C" void kernel_launch(void* const* d_in, const int* in_sizes, int n_in,
                              void* d_out, int out_size) {
    const float* x  = (const float*)d_in[0];
    const float* wh = (const float*)d_in[1];
    const float* ww = (const float*)d_in[2];
    const float* r  = (const float*)d_in[3];
    float* out = (float*)d_out;

    int nimg = in_sizes[0] / (HH * WW);   // B*C = 768

    dim3 blk(32, 2, 1);
    dim3 grd(2, 1, nimg);
    caxial_kernel<<<grd, blk>>>(x, wh, ww, r, out);
}

// round 4
// speedup vs baseline: 1.5426x; 1.5426x over previous
#include <cuda_runtime.h>
#include <cstdint>

#define CC 96
#define HH 256
#define WW 256
#define KK 7

__device__ __forceinline__ void fma2(unsigned long long &d,
                                     unsigned long long a,
                                     unsigned long long b) {
    asm("fma.rn.f32x2 %0, %1, %2, %0;" : "+l"(d) : "l"(a), "l"(b));
}
__device__ __forceinline__ unsigned long long pk2(float lo, float hi) {
    return (unsigned long long)__float_as_uint(lo) |
           ((unsigned long long)__float_as_uint(hi) << 32);
}
__device__ __forceinline__ void upk2(unsigned long long v, float &lo, float &hi) {
    lo = __uint_as_float((unsigned int)(v & 0xffffffffull));
    hi = __uint_as_float((unsigned int)(v >> 32));
}

// blockDim=(64,2), grid=(1,2,nimg). Thread: 4 cols (float4), 64-row strip.
// Fast path (r < 5/3): folded 12-tap integer-offset conv.
//   H conv: 16-slot register ring, prefetch 6 rows ahead (covers DRAM).
//   W conv: 15-col window; side values loaded 1 iteration ahead (L1 hits).
__global__ __launch_bounds__(128, 4) void caxial_kernel(const float* __restrict__ x,
                                                        const float* __restrict__ wh,
                                                        const float* __restrict__ ww,
                                                        const float* __restrict__ rp,
                                                        float* __restrict__ out) {
    const int c  = blockIdx.z % CC;
    const int tx = threadIdx.x;                               // 0..63
    const int strip = blockIdx.y * 2 + threadIdx.y;           // 0..3
    const int x4 = tx * 4;
    const int y0 = strip * 64;
    const float* xc = x   + (size_t)blockIdx.z * (HH * WW);
    float*       oc = out + (size_t)blockIdx.z * (HH * WW);

    float rv = rp[0];
    if (rv < 1.0f) rv = 1.0f;

    float whv[KK], wwv[KK], fri[KK];
    int   k0i[KK];
    #pragma unroll
    for (int i = 0; i < KK; i++) {
        float ofr = (float)(i - 3) * rv;
        float fl  = floorf(ofr);
        k0i[i] = (int)fl + 6;
        fri[i] = ofr - fl;
        whv[i] = wh[c * KK + i];
        wwv[i] = ww[c * KK + i];
    }
    const bool fast = (k0i[0] >= 0) && (k0i[KK - 1] + 1 <= 11);

    if (fast) {
        // Fold 7 bilinear taps into 12 integer-offset weights (dc/dr = k - 6)
        unsigned long long cwh2[12];
        float cww[12];
        #pragma unroll
        for (int k = 0; k < 12; k++) {
            float sh = 0.f, sw = 0.f;
            #pragma unroll
            for (int i = 0; i < KK; i++) {
                if (k0i[i] == k)     { sh += whv[i] * (1.f - fri[i]); sw += wwv[i] * (1.f - fri[i]); }
                if (k0i[i] + 1 == k) { sh += whv[i] * fri[i];         sw += wwv[i] * fri[i]; }
            }
            cwh2[k] = pk2(sh, sh);
            cww[k]  = sw;
        }

        // Register ring: 16 rows, one float4 each. slot(row) = row & 15.
        ulonglong2 ring[16];
        #pragma unroll
        for (int t = -6; t <= 5; t++) {
            int row = y0 + t;
            ulonglong2 v = make_ulonglong2(0ull, 0ull);
            if (row >= 0)   // row < HH always true in prologue (y0 <= 192)
                v = *reinterpret_cast<const ulonglong2*>(xc + (size_t)row * WW + x4);
            ring[(t + 16) & 15] = v;
        }

        // Side-load predicates (narrow loads: 2 + 4 + 4 + 1 floats)
        const bool eL2 = (x4 >= 8);          // cols x4-6, x4-5  (LDG.64, 8B aligned)
        const bool eL1 = (x4 >= 4);          // cols x4-4..x4-1  (LDG.128)
        const bool eR1 = (x4 <= WW - 8);     // cols x4+4..x4+7  (LDG.128)
        const bool eR2 = (x4 <= WW - 12);    // col  x4+8        (LDG.32)
        const float2 z2 = make_float2(0.f, 0.f);
        const float4 z4 = make_float4(0.f, 0.f, 0.f, 0.f);

        // Prologue: sides for first row (y0)
        const float* r0p = xc + (size_t)y0 * WW;
        float2 cl2 = eL2 ? *reinterpret_cast<const float2*>(r0p + x4 - 6) : z2;
        float4 cl1 = eL1 ? *reinterpret_cast<const float4*>(r0p + x4 - 4) : z4;
        float4 cr1 = eR1 ? *reinterpret_cast<const float4*>(r0p + x4 + 4) : z4;
        float  cr2 = eR2 ? r0p[x4 + 8] : 0.f;

        #pragma unroll 1
        for (int half = 0; half < 4; half++) {
            int ybase = y0 + half * 16;
            #pragma unroll
            for (int u = 0; u < 16; u++) {
                int y = ybase + u;

                // Ring prefetch: row y+6 into slot (u+6)&15
                {
                    int row = y + 6;
                    ulonglong2 v = make_ulonglong2(0ull, 0ull);
                    if (row < HH)
                        v = *reinterpret_cast<const ulonglong2*>(xc + (size_t)row * WW + x4);
                    ring[(u + 6) & 15] = v;
                }

                // Side prefetch: row y+1 (consumed next iteration; L1 hits)
                float2 nl2 = z2; float4 nl1 = z4, nr1 = z4; float nr2 = 0.f;
                {
                    int yn = y + 1;
                    if (yn < HH) {
                        const float* np = xc + (size_t)yn * WW;
                        if (eL2) nl2 = *reinterpret_cast<const float2*>(np + x4 - 6);
                        if (eL1) nl1 = *reinterpret_cast<const float4*>(np + x4 - 4);
                        if (eR1) nr1 = *reinterpret_cast<const float4*>(np + x4 + 4);
                        if (eR2) nr2 = np[x4 + 8];
                    }
                }

                ulonglong2 ctr = ring[u & 15];       // row y, cols x4..x4+3
                float c0, c1, c2, c3;
                upk2(ctr.x, c0, c1);
                upk2(ctr.y, c2, c3);

                // identity + H conv (packed f32x2 FMAs)
                unsigned long long acc01 = ctr.x;
                unsigned long long acc23 = ctr.y;
                #pragma unroll
                for (int k = 0; k < 12; k++) {       // row y + (k-6)
                    ulonglong2 rv2 = ring[(u + k + 10) & 15];
                    fma2(acc01, cwh2[k], rv2.x);
                    fma2(acc23, cwh2[k], rv2.y);
                }
                float a0, a1, a2, a3;
                upk2(acc01, a0, a1);
                upk2(acc23, a2, a3);

                // W conv: win[m] = col (x4 - 6 + m), m = 0..14
                float win[15];
                win[0]  = cl2.x; win[1]  = cl2.y;
                win[2]  = cl1.x; win[3]  = cl1.y; win[4]  = cl1.z; win[5]  = cl1.w;
                win[6]  = c0;    win[7]  = c1;    win[8]  = c2;    win[9]  = c3;
                win[10] = cr1.x; win[11] = cr1.y; win[12] = cr1.z; win[13] = cr1.w;
                win[14] = cr2;
                #pragma unroll
                for (int k = 0; k < 12; k++) {       // col (x4+j) + (k-6) = win[k+j]
                    float w = cww[k];
                    a0 += w * win[k];
                    a1 += w * win[k + 1];
                    a2 += w * win[k + 2];
                    a3 += w * win[k + 3];
                }

                __stcs(reinterpret_cast<float4*>(oc + (size_t)y * WW + x4),
                       make_float4(a0, a1, a2, a3));

                // rotate pipelined sides
                cl2 = nl2; cl1 = nl1; cr1 = nr1; cr2 = nr2;
            }
        }
    } else {
        // Generic path: direct 7-tap bilinear gather along both axes.
        #pragma unroll 1
        for (int yy = 0; yy < 64; yy++) {
            int y = y0 + yy;
            float acc[4];
            #pragma unroll
            for (int j = 0; j < 4; j++) acc[j] = xc[(size_t)y * WW + x4 + j];
            #pragma unroll
            for (int i = 0; i < KK; i++) {
                int   d  = k0i[i] - 6;
                float fr = fri[i];
                int r0 = y + d, r1 = r0 + 1;
                #pragma unroll
                for (int j = 0; j < 4; j++) {
                    int col = x4 + j;
                    float s0 = (r0 >= 0 && r0 < HH) ? xc[(size_t)r0 * WW + col] : 0.f;
                    float s1 = (r1 >= 0 && r1 < HH) ? xc[(size_t)r1 * WW + col] : 0.f;
                    acc[j] += whv[i] * (s0 * (1.f - fr) + s1 * fr);
                    int c0i = col + d, c1i = c0i + 1;
                    float t0 = (c0i >= 0 && c0i < WW) ? xc[(size_t)y * WW + c0i] : 0.f;
                    float t1 = (c1i >= 0 && c1i < WW) ? xc[(size_t)y * WW + c1i] : 0.f;
                    acc[j] += wwv[i] * (t0 * (1.f - fr) + t1 * fr);
                }
            }
            #pragma unroll
            for (int j = 0; j < 4; j++) oc[(size_t)y * WW + x4 + j] = acc[j];
        }
    }
}

extern "C" void kernel_launch(void* const* d_in, const int* in_sizes, int n_in,
                              void* d_out, int out_size) {
    const float* x  = (const float*)d_in[0];
    const float* wh = (const float*)d_in[1];
    const float* ww = (const float*)d_in[2];
    const float* r  = (const float*)d_in[3];
    float* out = (float*)d_out;

    int nimg = in_sizes[0] / (HH * WW);   // B*C = 768

    dim3 blk(64, 2, 1);
    dim3 grd(1, 2, nimg);
    caxial_kernel<<<grd, blk>>>(x, wh, ww, r, out);
}